// round 12
// baseline (speedup 1.0000x reference)
#include <cuda_runtime.h>
#include <cuda_fp16.h>
#include <cstdint>

#define K_DIM 1024
#define M_DIM 2048
#define N_DIM 1024
#define NCHUNK 64
#define NCTA   296          // 2 per SM exactly

// Operands stored in m16n8k16 fragment order.
// g_Ahi/g_Alo: [chunk][mfrag 0..127][lane 0..31] -> uint4 {a0a1,a2a3,a4a5,a6a7}
// g_Bfr:       [chunk][nfrag 0..127][lane 0..31] -> uint4 {whi0,whi1,wlo0,wlo1}
__device__ uint4 g_Ahi[(size_t)NCHUNK * 128 * 32];
__device__ uint4 g_Alo[(size_t)NCHUNK * 128 * 32];
__device__ uint4 g_Bfr[(size_t)NCHUNK * 128 * 32];

// ---------------------------------------------------------------------------
// Zero the output (harness poisons it; main kernel accumulates with atomicAdd)
// ---------------------------------------------------------------------------
__global__ void zero_out_kernel(float4* __restrict__ out) {
    int i = blockIdx.x * 256 + threadIdx.x;
    const float4 z = make_float4(0.f, 0.f, 0.f, 0.f);
#pragma unroll
    for (int k = 0; k < 4; k++) out[i + k * 131072] = z;
}

// ---------------------------------------------------------------------------
// Fused prep: blocks [0,512) do X, [512,768) do W (identical to R8).
// ---------------------------------------------------------------------------
__global__ void prep_kernel(const float* __restrict__ X,
                            const float* __restrict__ W,
                            const float* __restrict__ vmap,
                            const float* __restrict__ wmap) {
    __shared__ float s_lut[256];
    __shared__ unsigned sHi[256][9];
    __shared__ unsigned sLo[256][9];

    const int tid = threadIdx.x;
    const bool isX = blockIdx.x < 512;
    s_lut[tid] = isX ? vmap[tid] : wmap[tid];
    __syncthreads();

    unsigned hi[8], lo[8];
    if (isX) {
        const int b = blockIdx.x;
        const int r = b >> 3, m0b = (b & 7) * 256;
        const int m = m0b + tid;
        const float* src = X + (size_t)m * K_DIM + r * 16;
        float xs[16];
        ((float4*)xs)[0] = ((const float4*)src)[0];
        ((float4*)xs)[1] = ((const float4*)src)[1];
        ((float4*)xs)[2] = ((const float4*)src)[2];
        ((float4*)xs)[3] = ((const float4*)src)[3];
#pragma unroll
        for (int jj = 0; jj < 8; jj++) {
            unsigned short h[2], l[2];
#pragma unroll
            for (int e = 0; e < 2; e++) {
                int j = 2 * jj + e;
                float xv = xs[j];
                int idx = (int)(xv + 8.0f);
                idx = idx < 0 ? 0 : (idx > 15 ? 15 : idx);
                float xc = (xv + s_lut[j * 16 + idx]) * 0.0625f;
                __half hh = __float2half_rn(xc);
                __half ll = __float2half_rn(xc - __half2float(hh));
                h[e] = __half_as_ushort(hh);
                l[e] = __half_as_ushort(ll);
            }
            hi[jj] = h[0] | ((unsigned)h[1] << 16);
            lo[jj] = l[0] | ((unsigned)l[1] << 16);
        }
#pragma unroll
        for (int jj = 0; jj < 8; jj++) { sHi[tid][jj] = hi[jj]; sLo[tid][jj] = lo[jj]; }
        __syncthreads();

#pragma unroll
        for (int ss = 0; ss < 2; ss++) {
            int s = tid + 256 * ss;
            int f = s >> 5, l = s & 31, g = l >> 2, tq = l & 3;
            int r0 = f * 16 + g, r1 = r0 + 8;
            uint4 H = make_uint4(sHi[r0][tq], sHi[r1][tq], sHi[r0][tq + 4], sHi[r1][tq + 4]);
            uint4 L = make_uint4(sLo[r0][tq], sLo[r1][tq], sLo[r0][tq + 4], sLo[r1][tq + 4]);
            size_t gi = ((size_t)r * 128 + (m0b >> 4) + f) * 32 + l;
            g_Ahi[gi] = H;
            g_Alo[gi] = L;
        }
    } else {
        const int b = blockIdx.x - 512;
        const int r = b >> 2, n0b = (b & 3) * 256;
        const int n = n0b + tid;
#pragma unroll
        for (int jj = 0; jj < 8; jj++) {
            unsigned short h[2], l[2];
#pragma unroll
            for (int e = 0; e < 2; e++) {
                int j = 2 * jj + e;
                float w = W[(size_t)(16 * r + j) * N_DIM + n];
                int idx = (int)(w + 8.0f);
                idx = idx < 0 ? 0 : (idx > 15 ? 15 : idx);
                float wc = w + s_lut[j * 16 + idx];
                __half hh = __float2half_rn(wc);
                __half ll = __float2half_rn(wc - __half2float(hh));
                h[e] = __half_as_ushort(hh);
                l[e] = __half_as_ushort(ll);
            }
            hi[jj] = h[0] | ((unsigned)h[1] << 16);
            lo[jj] = l[0] | ((unsigned)l[1] << 16);
        }
#pragma unroll
        for (int jj = 0; jj < 8; jj++) { sHi[tid][jj] = hi[jj]; sLo[tid][jj] = lo[jj]; }
        __syncthreads();

#pragma unroll
        for (int ss = 0; ss < 4; ss++) {
            int s = tid + 256 * ss;
            int f = s >> 5, l = s & 31, g = l >> 2, tq = l & 3;
            int nl = f * 8 + g;
            uint4 V = make_uint4(sHi[nl][tq], sHi[nl][tq + 4], sLo[nl][tq], sLo[nl][tq + 4]);
            g_Bfr[((size_t)r * 128 + (n0b >> 3) + f) * 32 + l] = V;
        }
    }
}

// ---------------------------------------------------------------------------
#define MMA_INIT(C, A, B0, B1, Z)                                              \
    asm("mma.sync.aligned.m16n8k16.row.col.f32.f16.f16.f32 "                   \
        "{%0,%1,%2,%3}, {%4,%5,%6,%7}, {%8,%9}, {%10,%10,%10,%10};"            \
        : "=f"((C)[0]), "=f"((C)[1]), "=f"((C)[2]), "=f"((C)[3])               \
        : "r"((A).x), "r"((A).y), "r"((A).z), "r"((A).w), "r"(B0), "r"(B1),    \
          "f"(Z))

#define MMA_ACC(C, A, B0, B1)                                                  \
    asm("mma.sync.aligned.m16n8k16.row.col.f32.f16.f16.f32 "                   \
        "{%0,%1,%2,%3}, {%4,%5,%6,%7}, {%8,%9}, {%0,%1,%2,%3};"                \
        : "+f"((C)[0]), "+f"((C)[1]), "+f"((C)[2]), "+f"((C)[3])               \
        : "r"((A).x), "r"((A).y), "r"((A).z), "r"((A).w), "r"(B0), "r"(B1))

// ---------------------------------------------------------------------------
// Main: persistent balanced split. 296 CTAs, each takes 55-56 consecutive
// (tile, chunk) units (tile-major). Partial per-tile ADC sums flushed with
// atomicAdd (exact small integers -> deterministic). No smem, no barriers.
// ---------------------------------------------------------------------------
__global__ void __launch_bounds__(256, 2)
opu_main_kernel(float* __restrict__ out) {
    const int t = threadIdx.x, wid = t >> 5, lane = t & 31;
    const int wm = (wid >> 1) * 32, wn = (wid & 1) * 32;

    const int c = blockIdx.x;
    // 104 CTAs * 56 + 192 CTAs * 55 = 16384
    int start = (c < 104) ? 56 * c : 5824 + 55 * (c - 104);
    const int end = start + ((c < 104) ? 56 : 55);

    const float FZ = 0.0f;
    const float MAGIC = 12582912.0f;   // 1.5*2^23
    const size_t CSTR = 128 * 32;

    int u = start;
    while (u < end) {
        const int tile = u >> 6;
        const int c0 = u & 63;
        int nch = end - u; if (nch > NCHUNK - c0) nch = NCHUNK - c0;
        const int clast = c0 + nch;

        const int m0 = (tile >> 4) * 128, n0 = (tile & 15) * 64;
        const int mf = (m0 + wm) >> 4;
        const int nf = (n0 + wn) >> 3;
        const uint4* pA0 = g_Ahi + (size_t)mf * 32 + lane;
        const uint4* pA1 = g_Alo + (size_t)mf * 32 + lane;
        const uint4* pB  = g_Bfr + (size_t)nf * 32 + lane;

        unsigned su[2][4][4];
#pragma unroll
        for (int i = 0; i < 2; i++)
#pragma unroll
            for (int j = 0; j < 4; j++)
#pragma unroll
                for (int e = 0; e < 4; e++) su[i][j][e] = 0u;

        uint4 AH[2][2], AL[2][2], BF[2][4];

#define LOAD_CHUNK(buf, r)                                                     \
        do {                                                                   \
            const size_t o = (size_t)(r) * CSTR;                               \
            AH[buf][0] = pA0[o];        AH[buf][1] = pA0[o + 32];              \
            AL[buf][0] = pA1[o];        AL[buf][1] = pA1[o + 32];              \
            BF[buf][0] = pB[o];         BF[buf][1] = pB[o + 32];               \
            BF[buf][2] = pB[o + 64];    BF[buf][3] = pB[o + 96];               \
        } while (0)

#define COMPUTE_CHUNK(buf)                                                     \
        do {                                                                   \
            _Pragma("unroll")                                                  \
            for (int i = 0; i < 2; i++) {                                      \
                _Pragma("unroll")                                              \
                for (int jp = 0; jp < 2; jp++) {                               \
                    float a0[4], a1[4];                                        \
                    const uint4 b0 = BF[buf][2 * jp], b1 = BF[buf][2 * jp + 1];\
                    MMA_INIT(a0, AH[buf][i], b0.x, b0.y, FZ);                  \
                    MMA_INIT(a1, AH[buf][i], b1.x, b1.y, FZ);                  \
                    MMA_ACC(a0, AH[buf][i], b0.z, b0.w);                       \
                    MMA_ACC(a1, AH[buf][i], b1.z, b1.w);                       \
                    MMA_ACC(a0, AL[buf][i], b0.x, b0.y);                       \
                    MMA_ACC(a1, AL[buf][i], b1.x, b1.y);                       \
                    _Pragma("unroll")                                          \
                    for (int e = 0; e < 4; e++) {                              \
                        su[i][2 * jp][e]     += __float_as_uint(a0[e] + MAGIC);\
                        su[i][2 * jp + 1][e] += __float_as_uint(a1[e] + MAGIC);\
                    }                                                          \
                }                                                              \
            }                                                                  \
        } while (0)

        LOAD_CHUNK(c0 & 1, c0);   // buffer index == r & 1, also for first chunk
        for (int r = c0; r < clast; r++) {
            if (r + 1 < clast) LOAD_CHUNK((r + 1) & 1, r + 1);
            COMPUTE_CHUNK(r & 1);
        }

        // flush: value = 16 * (su - nch*0x4B400000 mod 2^32); exact integers
        const unsigned bias = (unsigned)nch * 0x4B400000u;
        const int g = lane >> 2, tg = lane & 3;
#pragma unroll
        for (int i = 0; i < 2; i++)
#pragma unroll
            for (int h = 0; h < 2; h++) {
                int row = m0 + wm + 16 * i + 8 * h + g;
                float* orow = out + (size_t)row * N_DIM + n0 + wn + 2 * tg;
#pragma unroll
                for (int j = 0; j < 4; j++) {
                    atomicAdd(orow + 8 * j,
                              16.0f * (float)(int)(su[i][j][2 * h + 0] - bias));
                    atomicAdd(orow + 8 * j + 1,
                              16.0f * (float)(int)(su[i][j][2 * h + 1] - bias));
                }
            }

        u += nch;
#undef LOAD_CHUNK
#undef COMPUTE_CHUNK
    }
}

// ---------------------------------------------------------------------------
extern "C" void kernel_launch(void* const* d_in, const int* in_sizes, int n_in,
                              void* d_out, int out_size) {
    const float* X    = (const float*)d_in[0];  // (2,1024,1024)
    const float* W    = (const float*)d_in[1];  // (1024,1024)
    const float* vmap = (const float*)d_in[2];  // (16,16)
    const float* wmap = (const float*)d_in[3];  // (16,16)
    float* out = (float*)d_out;                 // (2,1024,1024)

    zero_out_kernel<<<512, 256>>>((float4*)out);
    prep_kernel<<<768, 256>>>(X, W, vmap, wmap);
    opu_main_kernel<<<NCTA, 256>>>(out);
}

// round 13
// speedup vs baseline: 1.8750x; 1.8750x over previous
#include <cuda_runtime.h>
#include <cuda_fp16.h>
#include <cstdint>

#define K_DIM 1024
#define M_DIM 2048
#define N_DIM 1024
#define NCHUNK 64

// m16n8k16 fragment layout.
// g_Afr: [chunk][mfrag 0..127][plane hi/lo][lane] -> uint4
// g_Bfr: [chunk][nfrag 0..127][lane] -> uint4 {whi0,whi1,wlo0,wlo1}
__device__ uint4 g_Afr[(size_t)NCHUNK * 128 * 2 * 32];
__device__ uint4 g_Bfr[(size_t)NCHUNK * 128 * 32];

// ---------------------------------------------------------------------------
// Fused prep: blocks [0,512) do X, [512,768) do W. LUT in smem.
// ---------------------------------------------------------------------------
__global__ void prep_kernel(const float* __restrict__ X,
                            const float* __restrict__ W,
                            const float* __restrict__ vmap,
                            const float* __restrict__ wmap) {
    __shared__ float s_lut[256];
    __shared__ unsigned sHi[256][9];
    __shared__ unsigned sLo[256][9];

    const int tid = threadIdx.x;
    const bool isX = blockIdx.x < 512;
    s_lut[tid] = isX ? vmap[tid] : wmap[tid];
    __syncthreads();

    unsigned hi[8], lo[8];
    if (isX) {
        const int b = blockIdx.x;
        const int r = b >> 3, m0b = (b & 7) * 256;
        const int m = m0b + tid;
        const float* src = X + (size_t)m * K_DIM + r * 16;
        float xs[16];
        ((float4*)xs)[0] = ((const float4*)src)[0];
        ((float4*)xs)[1] = ((const float4*)src)[1];
        ((float4*)xs)[2] = ((const float4*)src)[2];
        ((float4*)xs)[3] = ((const float4*)src)[3];
#pragma unroll
        for (int jj = 0; jj < 8; jj++) {
            unsigned short h[2], l[2];
#pragma unroll
            for (int e = 0; e < 2; e++) {
                int j = 2 * jj + e;
                float xv = xs[j];
                int idx = (int)(xv + 8.0f);
                idx = idx < 0 ? 0 : (idx > 15 ? 15 : idx);
                float xc = (xv + s_lut[j * 16 + idx]) * 0.0625f;
                __half hh = __float2half_rn(xc);
                __half ll = __float2half_rn(xc - __half2float(hh));
                h[e] = __half_as_ushort(hh);
                l[e] = __half_as_ushort(ll);
            }
            hi[jj] = h[0] | ((unsigned)h[1] << 16);
            lo[jj] = l[0] | ((unsigned)l[1] << 16);
        }
#pragma unroll
        for (int jj = 0; jj < 8; jj++) { sHi[tid][jj] = hi[jj]; sLo[tid][jj] = lo[jj]; }
        __syncthreads();

#pragma unroll
        for (int ss = 0; ss < 2; ss++) {
            int s = tid + 256 * ss;
            int f = s >> 5, l = s & 31, g = l >> 2, tq = l & 3;
            int r0 = f * 16 + g, r1 = r0 + 8;
            uint4 H = make_uint4(sHi[r0][tq], sHi[r1][tq], sHi[r0][tq + 4], sHi[r1][tq + 4]);
            uint4 L = make_uint4(sLo[r0][tq], sLo[r1][tq], sLo[r0][tq + 4], sLo[r1][tq + 4]);
            size_t base = ((size_t)r * 128 + (m0b >> 4) + f) * 64 + l;
            g_Afr[base] = H;          // hi plane
            g_Afr[base + 32] = L;     // lo plane
        }
    } else {
        const int b = blockIdx.x - 512;
        const int r = b >> 2, n0b = (b & 3) * 256;
        const int n = n0b + tid;
#pragma unroll
        for (int jj = 0; jj < 8; jj++) {
            unsigned short h[2], l[2];
#pragma unroll
            for (int e = 0; e < 2; e++) {
                int j = 2 * jj + e;
                float w = W[(size_t)(16 * r + j) * N_DIM + n];
                int idx = (int)(w + 8.0f);
                idx = idx < 0 ? 0 : (idx > 15 ? 15 : idx);
                float wc = w + s_lut[j * 16 + idx];
                __half hh = __float2half_rn(wc);
                __half ll = __float2half_rn(wc - __half2float(hh));
                h[e] = __half_as_ushort(hh);
                l[e] = __half_as_ushort(ll);
            }
            hi[jj] = h[0] | ((unsigned)h[1] << 16);
            lo[jj] = l[0] | ((unsigned)l[1] << 16);
        }
#pragma unroll
        for (int jj = 0; jj < 8; jj++) { sHi[tid][jj] = hi[jj]; sLo[tid][jj] = lo[jj]; }
        __syncthreads();

#pragma unroll
        for (int ss = 0; ss < 4; ss++) {
            int s = tid + 256 * ss;
            int f = s >> 5, l = s & 31, g = l >> 2, tq = l & 3;
            int nl = f * 8 + g;
            uint4 V = make_uint4(sHi[nl][tq], sHi[nl][tq + 4], sLo[nl][tq], sLo[nl][tq + 4]);
            g_Bfr[((size_t)r * 128 + (n0b >> 3) + f) * 32 + l] = V;
        }
    }
}

// ---------------------------------------------------------------------------
#define MMA_INIT(C, A, B0, B1, Z)                                              \
    asm("mma.sync.aligned.m16n8k16.row.col.f32.f16.f16.f32 "                   \
        "{%0,%1,%2,%3}, {%4,%5,%6,%7}, {%8,%9}, {%10,%10,%10,%10};"            \
        : "=f"((C)[0]), "=f"((C)[1]), "=f"((C)[2]), "=f"((C)[3])               \
        : "r"((A).x), "r"((A).y), "r"((A).z), "r"((A).w), "r"(B0), "r"(B1),    \
          "f"(Z))

#define MMA_ACC(C, A, B0, B1)                                                  \
    asm("mma.sync.aligned.m16n8k16.row.col.f32.f16.f16.f32 "                   \
        "{%0,%1,%2,%3}, {%4,%5,%6,%7}, {%8,%9}, {%0,%1,%2,%3};"                \
        : "+f"((C)[0]), "+f"((C)[1]), "+f"((C)[2]), "+f"((C)[3])               \
        : "r"((A).x), "r"((A).y), "r"((A).z), "r"((A).w), "r"(B0), "r"(B1))

// ---------------------------------------------------------------------------
// Main: fine-grained CTAs. 128 threads (4 warps, each 16m x 32n), CTA tile
// 64m x 32n, grid (32,32) = 1024 CTAs, 6 CTAs/SM (24 warps). No smem, no
// barriers, no atomics; each CTA owns its outputs. Static double buffering.
// ---------------------------------------------------------------------------
__global__ void __launch_bounds__(128, 6)
opu_main_kernel(float* __restrict__ out) {
    const int t = threadIdx.x, wid = t >> 5, lane = t & 31;
    const int bx = blockIdx.x;          // m tile (64 rows)
    const int by = blockIdx.y;          // n tile (32 cols)

    const int mf = bx * 4 + wid;        // this warp's mfrag
    const int nfb = by * 4;             // 4 nfrags

    const uint4* pA = g_Afr + (size_t)mf * 64 + lane;
    const uint4* pB = g_Bfr + (size_t)nfb * 32 + lane;
    const size_t ASTR = 128 * 64;       // uint4 per chunk (A)
    const size_t BSTR = 128 * 32;       // uint4 per chunk (B)

    unsigned su[4][4];
#pragma unroll
    for (int j = 0; j < 4; j++)
#pragma unroll
        for (int e = 0; e < 4; e++) su[j][e] = 0u;

    const float FZ = 0.0f;
    const float MAGIC = 12582912.0f;    // 1.5*2^23

    uint4 AH[2], AL[2], BF[2][4];

#define LOAD_CHUNK(buf, r)                                                     \
    do {                                                                       \
        const size_t oa = (size_t)(r) * ASTR;                                  \
        const size_t ob = (size_t)(r) * BSTR;                                  \
        AH[buf] = pA[oa];          AL[buf] = pA[oa + 32];                      \
        BF[buf][0] = pB[ob];       BF[buf][1] = pB[ob + 32];                   \
        BF[buf][2] = pB[ob + 64];  BF[buf][3] = pB[ob + 96];                   \
    } while (0)

#define COMPUTE_CHUNK(buf)                                                     \
    do {                                                                       \
        _Pragma("unroll")                                                      \
        for (int jp = 0; jp < 2; jp++) {                                       \
            float a0[4], a1[4];                                                \
            const uint4 b0 = BF[buf][2 * jp], b1 = BF[buf][2 * jp + 1];        \
            MMA_INIT(a0, AH[buf], b0.x, b0.y, FZ);   /* hi*whi */              \
            MMA_INIT(a1, AH[buf], b1.x, b1.y, FZ);                             \
            MMA_ACC(a0, AH[buf], b0.z, b0.w);        /* hi*wlo */              \
            MMA_ACC(a1, AH[buf], b1.z, b1.w);                                  \
            MMA_ACC(a0, AL[buf], b0.x, b0.y);        /* lo*whi */              \
            MMA_ACC(a1, AL[buf], b1.x, b1.y);                                  \
            _Pragma("unroll")                                                  \
            for (int e = 0; e < 4; e++) {                                      \
                su[2 * jp][e]     += __float_as_uint(a0[e] + MAGIC);           \
                su[2 * jp + 1][e] += __float_as_uint(a1[e] + MAGIC);           \
            }                                                                  \
        }                                                                      \
    } while (0)

    LOAD_CHUNK(0, 0);
    for (int r = 0; r < NCHUNK; r += 2) {
        LOAD_CHUNK(1, r + 1);
        COMPUTE_CHUNK(0);
        int r2 = (r + 2 < NCHUNK) ? r + 2 : NCHUNK - 1;
        LOAD_CHUNK(0, r2);
        COMPUTE_CHUNK(1);
    }

    // out = 16 * (su - 64*0x4B400000 mod 2^32)
    const unsigned BIAS64 = 0xD0000000u;
    const int g = lane >> 2, tg = lane & 3;
    const int m0 = bx * 64 + wid * 16;
    const int n0 = by * 32;
#pragma unroll
    for (int h = 0; h < 2; h++) {
        int row = m0 + 8 * h + g;
        float* orow = out + (size_t)row * N_DIM + n0 + 2 * tg;
#pragma unroll
        for (int j = 0; j < 4; j++) {
            float2 o;
            o.x = 16.0f * (float)(int)(su[j][2 * h + 0] - BIAS64);
            o.y = 16.0f * (float)(int)(su[j][2 * h + 1] - BIAS64);
            *(float2*)(orow + 8 * j) = o;
        }
    }
#undef LOAD_CHUNK
#undef COMPUTE_CHUNK
}

// ---------------------------------------------------------------------------
extern "C" void kernel_launch(void* const* d_in, const int* in_sizes, int n_in,
                              void* d_out, int out_size) {
    const float* X    = (const float*)d_in[0];  // (2,1024,1024)
    const float* W    = (const float*)d_in[1];  // (1024,1024)
    const float* vmap = (const float*)d_in[2];  // (16,16)
    const float* wmap = (const float*)d_in[3];  // (16,16)
    float* out = (float*)d_out;                 // (2,1024,1024)

    prep_kernel<<<768, 256>>>(X, W, vmap, wmap);
    opu_main_kernel<<<dim3(32, 32), 128>>>(out);
}